// round 4
// baseline (speedup 1.0000x reference)
#include <cuda_runtime.h>
#include <math.h>

// Problem constants
#define Sn 8192
#define Dn 2048
#define En 64
#define Cn 128
#define MAXN 1024   // max tokens gathered per expert (mean 128, sigma ~11)

static const long long SECn = (long long)Sn * En * Cn;  // 67,108,864

// ---------------- device scratch (no allocations allowed) ----------------
__device__ float g_part[2 * Sn * En];   // split-K partial logits, 4MB
__device__ float g_gate[Sn];            // gate value at argmax expert
__device__ int   g_list[En * MAXN];     // per-expert gathered token indices
__device__ float g_colsum[En];          // column sums of gates (for me)
__device__ int   g_cnt[En];             // raw expert counts (mask1 sums)

// ---------------- GEMM: logits = x @ wg^T, split-K=2 ----------------
// grid (128, 2), block 256. Tile: 64 tokens x 64 experts, K-chunk 32.
// Accumulation order identical to R2/R3 (bit-faithful argmax).
// Block (0,0) also zeroes the per-expert accumulators (init fold-in).
__global__ __launch_bounds__(256) void gemm_kernel(const float* __restrict__ x,
                                                   const float* __restrict__ wg) {
    if (blockIdx.x == 0 && blockIdx.y == 0 && threadIdx.x < En) {
        g_colsum[threadIdx.x] = 0.f;
        g_cnt[threadIdx.x] = 0;
    }

    const int m0 = blockIdx.x * 64;
    const int k0 = blockIdx.y * 1024;
    __shared__ float xsT[32][68];
    __shared__ float wsT[32][68];

    const int tid = threadIdx.x;
    const int tx = tid & 15;   // expert group
    const int ty = tid >> 4;   // token group

    float acc[4][4];
#pragma unroll
    for (int i = 0; i < 4; i++)
#pragma unroll
        for (int j = 0; j < 4; j++) acc[i][j] = 0.f;

    for (int kb = 0; kb < 1024; kb += 32) {
#pragma unroll
        for (int i = 0; i < 2; i++) {
            int v = tid + i * 256;       // 0..511
            int row = v >> 3;            // 0..63
            int kq = v & 7;              // 0..7 (float4 along K)
            const float4 xv = *(const float4*)(x + (size_t)(m0 + row) * Dn + (k0 + kb + (kq << 2)));
            xsT[(kq << 2) + 0][row] = xv.x;
            xsT[(kq << 2) + 1][row] = xv.y;
            xsT[(kq << 2) + 2][row] = xv.z;
            xsT[(kq << 2) + 3][row] = xv.w;
            const float4 wv = *(const float4*)(wg + (size_t)row * Dn + (k0 + kb + (kq << 2)));
            wsT[(kq << 2) + 0][row] = wv.x;
            wsT[(kq << 2) + 1][row] = wv.y;
            wsT[(kq << 2) + 2][row] = wv.z;
            wsT[(kq << 2) + 3][row] = wv.w;
        }
        __syncthreads();
#pragma unroll
        for (int kk = 0; kk < 32; kk++) {
            float4 a = *(const float4*)&xsT[kk][ty << 2];
            float4 b = *(const float4*)&wsT[kk][tx << 2];
            float av[4] = {a.x, a.y, a.z, a.w};
            float bv[4] = {b.x, b.y, b.z, b.w};
#pragma unroll
            for (int i = 0; i < 4; i++)
#pragma unroll
                for (int j = 0; j < 4; j++)
                    acc[i][j] = fmaf(av[i], bv[j], acc[i][j]);
        }
        __syncthreads();
    }

    float* op = g_part + (size_t)blockIdx.y * (Sn * En);
#pragma unroll
    for (int i = 0; i < 4; i++) {
        float4 vv = make_float4(acc[i][0], acc[i][1], acc[i][2], acc[i][3]);
        *(float4*)(op + (size_t)(m0 + (ty << 2) + i) * En + (tx << 2)) = vv;
    }
}

// ---------------- softmax + argmax + column sums + counts + expert lists ----------------
// one warp per token, 8 tokens per block, 1024 blocks
__global__ __launch_bounds__(256) void softmax_kernel() {
    __shared__ float scs[En];
    const int warp = threadIdx.x >> 5;
    const int lane = threadIdx.x & 31;
    const int s = blockIdx.x * 8 + warp;

    if (threadIdx.x < En) scs[threadIdx.x] = 0.f;
    __syncthreads();

    const float* p0 = g_part + (size_t)s * En;
    const float* p1 = g_part + (size_t)(Sn * En) + (size_t)s * En;
    float v0 = p0[lane] + p1[lane];
    float v1 = p0[lane + 32] + p1[lane + 32];

    // row max
    float m = fmaxf(v0, v1);
#pragma unroll
    for (int o = 16; o; o >>= 1) m = fmaxf(m, __shfl_xor_sync(0xffffffffu, m, o));

    float e0 = expf(v0 - m), e1 = expf(v1 - m);
    float ss = e0 + e1;
#pragma unroll
    for (int o = 16; o; o >>= 1) ss += __shfl_xor_sync(0xffffffffu, ss, o);
    float inv = 1.0f / ss;
    float gg0 = e0 * inv, gg1 = e1 * inv;

    // argmax with tie-break: smallest index (matches jnp.argmax)
    float bv; int bi;
    if (v0 >= v1) { bv = v0; bi = lane; } else { bv = v1; bi = lane + 32; }
#pragma unroll
    for (int o = 16; o; o >>= 1) {
        float ov = __shfl_xor_sync(0xffffffffu, bv, o);
        int oi = __shfl_xor_sync(0xffffffffu, bi, o);
        if (ov > bv || (ov == bv && oi < bi)) { bv = ov; bi = oi; }
    }
    // gate value at argmax (bi is warp-uniform now)
    float gsel = __shfl_sync(0xffffffffu, (bi < 32) ? gg0 : gg1, bi & 31);

    // block-level column sums, then one global atomic per expert per block
    atomicAdd(&scs[lane], gg0);
    atomicAdd(&scs[lane + 32], gg1);

    if (lane == 0) {
        g_gate[s] = gsel;
        int p = atomicAdd(&g_cnt[bi], 1);
        if (p < MAXN) g_list[bi * MAXN + p] = s;
    }
    __syncthreads();
    if (threadIdx.x < En) atomicAdd(&g_colsum[threadIdx.x], scs[threadIdx.x]);
}

// ---------------- exact JAX threefry2x32 noise (partitionable path) ----------------
__device__ __forceinline__ unsigned rotl32(unsigned v, int d) {
    return (v << d) | (v >> (32 - d));
}
__device__ __forceinline__ float jax_noise(int s, int e) {
    unsigned x0 = 0u;
    unsigned x1 = (unsigned)(s * En + e);

    const unsigned ks0 = 0u;
    const unsigned ks1 = 42u;
    const unsigned ks2 = 0u ^ 42u ^ 0x1BD11BDAu;

    x0 += ks0; x1 += ks1;
#define TF_ROUND(R) { x0 += x1; x1 = rotl32(x1, R); x1 ^= x0; }
    TF_ROUND(13) TF_ROUND(15) TF_ROUND(26) TF_ROUND(6)
    x0 += ks1; x1 += ks2 + 1u;
    TF_ROUND(17) TF_ROUND(29) TF_ROUND(16) TF_ROUND(24)
    x0 += ks2; x1 += ks0 + 2u;
    TF_ROUND(13) TF_ROUND(15) TF_ROUND(26) TF_ROUND(6)
    x0 += ks0; x1 += ks1 + 3u;
    TF_ROUND(17) TF_ROUND(29) TF_ROUND(16) TF_ROUND(24)
    x0 += ks1; x1 += ks2 + 4u;
    TF_ROUND(13) TF_ROUND(15) TF_ROUND(26) TF_ROUND(6)
    x0 += ks2; x1 += ks0 + 5u;
#undef TF_ROUND
    unsigned bits = x0 ^ x1;
    return __uint_as_float((bits >> 9) | 0x3F800000u) - 1.0f;
}

// ---------------- per-expert capacity selection + direct scatter + finalize ----------------
// one block per expert; reads prebuilt list, ranks by (noise desc, index asc),
// assigns slots by token-index rank among kept, writes nonzeros directly.
// Runs after the memset join, so every write lands on zeroed memory.
// Block 0 additionally writes l_aux and exp_counts.
__global__ __launch_bounds__(256) void capacity_kernel(float* __restrict__ out,
                                                       long long out_size) {
    const int e = blockIdx.x;
    __shared__ int   sidx[MAXN];
    __shared__ float snoi[MAXN];
    __shared__ char  skeep[MAXN];
    __shared__ float sv[En];

    int n = g_cnt[e];
    if (n > MAXN) n = MAXN;

    for (int i = threadIdx.x; i < n; i += blockDim.x) {
        int s = g_list[e * MAXN + i];
        sidx[i] = s;
        snoi[i] = jax_noise(s, e);
    }
    __syncthreads();

    // keep = rank < capacity by (noise desc, index asc); lax.top_k is index-stable
    for (int i = threadIdx.x; i < n; i += blockDim.x) {
        char k = 1;
        if (n > Cn) {
            int r = 0;
            float ni = snoi[i];
            int ii = sidx[i];
            for (int jj = 0; jj < n; jj++) {
                float nj = snoi[jj];
                r += (nj > ni) || (nj == ni && sidx[jj] < ii);
            }
            k = (r < Cn) ? 1 : 0;
        }
        skeep[i] = k;
    }
    __syncthreads();

    // slot = rank by token index among kept (cumsum semantics); scatter outputs
    for (int i = threadIdx.x; i < n; i += blockDim.x) {
        if (!skeep[i]) continue;
        int ii = sidx[i];
        int slot = 0;
        for (int jj = 0; jj < n; jj++) slot += (skeep[jj] && sidx[jj] < ii);
        long long r = (long long)ii * En + e;
        long long p = 1 + r * (long long)Cn + slot;
        if (p < out_size) out[p] = g_gate[ii];
        if (p + SECn < out_size) out[p + SECn] = 1.0f;
    }

    // finalize fold-in: l_aux + exp_counts (block 0 only)
    if (e == 0) {
        int t = threadIdx.x;
        if (t < En) sv[t] = g_colsum[t] * (float)g_cnt[t];
        __syncthreads();
        if (t == 0) {
            float sum = 0.f;
            for (int i = 0; i < En; i++) sum += sv[i];
            float laux = sum * ((float)En / ((float)Sn * (float)Sn));
            if (out_size > 0) out[0] = laux;
        }
        long long idx = 1 + 2 * SECn + t;
        if (t < En && idx < out_size) out[idx] = (float)g_cnt[t];
    }
}

// ---------------- launch ----------------
// Fork a second stream carrying one big cudaMemsetAsync (zero-fill of the whole
// output) that runs concurrently with the GEMM+softmax branch; join before the
// scatter. Event fork/join is the graph-capture-legal cross-stream pattern.
extern "C" void kernel_launch(void* const* d_in, const int* in_sizes, int n_in,
                              void* d_out, int out_size) {
    const float* x  = (const float*)d_in[0];   // [S, D] f32
    const float* wg = (const float*)d_in[1];   // [E, D] f32
    float* out = (float*)d_out;
    long long osz = (long long)out_size;

    static cudaStream_t s_fill = nullptr;
    static cudaEvent_t ev_fork = nullptr, ev_join = nullptr;
    if (s_fill == nullptr) {
        cudaStreamCreateWithFlags(&s_fill, cudaStreamNonBlocking);
        cudaEventCreateWithFlags(&ev_fork, cudaEventDisableTiming);
        cudaEventCreateWithFlags(&ev_join, cudaEventDisableTiming);
    }

    // fork: zero-fill the entire output buffer on the side stream
    cudaEventRecord(ev_fork, 0);
    cudaStreamWaitEvent(s_fill, ev_fork, 0);
    cudaMemsetAsync(d_out, 0, (size_t)osz * sizeof(float), s_fill);
    cudaEventRecord(ev_join, s_fill);

    // main branch: gating compute
    gemm_kernel<<<dim3(128, 2), 256>>>(x, wg);
    softmax_kernel<<<1024, 256>>>();

    // join: scatter must land on zeroed memory
    cudaStreamWaitEvent(0, ev_join, 0);
    capacity_kernel<<<En, 256>>>(out, osz);
}

// round 5
// speedup vs baseline: 1.0631x; 1.0631x over previous
#include <cuda_runtime.h>
#include <math.h>

// Problem constants
#define Sn 8192
#define Dn 2048
#define En 64
#define Cn 128
#define MAXN 1024   // max tokens gathered per expert (mean 128, sigma ~11)

#define GEMM_BLOCKS 256
#define FILL_BLOCKS 768
#define TOTAL_BLOCKS (GEMM_BLOCKS + FILL_BLOCKS)

static const long long SECn = (long long)Sn * En * Cn;  // 67,108,864

// ---------------- device scratch (no allocations allowed) ----------------
__device__ float g_part[2 * Sn * En];   // split-K partial logits, 4MB
__device__ float g_gate[Sn];            // gate value at argmax expert
__device__ int   g_list[En * MAXN];     // per-expert gathered token indices
__device__ float g_colsum[En];          // column sums of gates (for me)
__device__ int   g_cnt[En];             // raw expert counts (mask1 sums)

// ---------------- fused GEMM + zero-fill (block specialization) ----------------
// 1024 blocks x 256 threads. bid%4==0 -> GEMM block (256 of them, split-K=2,
// 64x64 tile, FMA order identical to the R2 passing kernel -> bit-faithful
// argmax). Other 768 blocks stream float4 zeros over the whole output buffer.
// GEMM (FMA/LDS-bound) and fill (DRAM-write-bound) use disjoint resources and
// co-reside on each SM, so they overlap at the hardware level.
__global__ __launch_bounds__(256) void gemm_fill_kernel(const float* __restrict__ x,
                                                        const float* __restrict__ wg,
                                                        float* __restrict__ out,
                                                        long long out_size) {
    __shared__ float xsT[32][68];
    __shared__ float wsT[32][68];

    const int bid = blockIdx.x;
    const int tid = threadIdx.x;

    if ((bid & 3) != 0) {
        // ---- fill block ----
        const long long fid = bid - (bid >> 2) - 1;      // 0..767
        const long long n4 = out_size >> 2;              // float4 count
        const long long stride = (long long)FILL_BLOCKS * 256;
        const float4 z4 = make_float4(0.f, 0.f, 0.f, 0.f);
        for (long long i = fid * 256 + tid; i < n4; i += stride)
            *(float4*)(out + (i << 2)) = z4;
        if (fid == 0 && tid < 4) {
            long long p = (n4 << 2) + tid;               // scalar tail
            if (p < out_size) out[p] = 0.f;
        }
        return;
    }

    // ---- GEMM block ----
    const int gid = bid >> 2;               // 0..255
    const int m0 = (gid & 127) * 64;
    const int k0 = (gid >> 7) * 1024;

    if (gid == 0 && tid < En) {             // init fold-in
        g_colsum[tid] = 0.f;
        g_cnt[tid] = 0;
    }

    const int tx = tid & 15;   // expert group
    const int ty = tid >> 4;   // token group

    float acc[4][4];
#pragma unroll
    for (int i = 0; i < 4; i++)
#pragma unroll
        for (int j = 0; j < 4; j++) acc[i][j] = 0.f;

    for (int kb = 0; kb < 1024; kb += 32) {
#pragma unroll
        for (int i = 0; i < 2; i++) {
            int v = tid + i * 256;       // 0..511
            int row = v >> 3;            // 0..63
            int kq = v & 7;              // 0..7 (float4 along K)
            const float4 xv = *(const float4*)(x + (size_t)(m0 + row) * Dn + (k0 + kb + (kq << 2)));
            xsT[(kq << 2) + 0][row] = xv.x;
            xsT[(kq << 2) + 1][row] = xv.y;
            xsT[(kq << 2) + 2][row] = xv.z;
            xsT[(kq << 2) + 3][row] = xv.w;
            const float4 wv = *(const float4*)(wg + (size_t)row * Dn + (k0 + kb + (kq << 2)));
            wsT[(kq << 2) + 0][row] = wv.x;
            wsT[(kq << 2) + 1][row] = wv.y;
            wsT[(kq << 2) + 2][row] = wv.z;
            wsT[(kq << 2) + 3][row] = wv.w;
        }
        __syncthreads();
#pragma unroll
        for (int kk = 0; kk < 32; kk++) {
            float4 a = *(const float4*)&xsT[kk][ty << 2];
            float4 b = *(const float4*)&wsT[kk][tx << 2];
            float av[4] = {a.x, a.y, a.z, a.w};
            float bv[4] = {b.x, b.y, b.z, b.w};
#pragma unroll
            for (int i = 0; i < 4; i++)
#pragma unroll
                for (int j = 0; j < 4; j++)
                    acc[i][j] = fmaf(av[i], bv[j], acc[i][j]);
        }
        __syncthreads();
    }

    float* op = g_part + (size_t)(gid >> 7) * (Sn * En);
#pragma unroll
    for (int i = 0; i < 4; i++) {
        float4 vv = make_float4(acc[i][0], acc[i][1], acc[i][2], acc[i][3]);
        *(float4*)(op + (size_t)(m0 + (ty << 2) + i) * En + (tx << 2)) = vv;
    }
}

// ---------------- softmax + argmax + column sums + counts + expert lists ----------------
// one warp per token, 8 tokens per block, 1024 blocks
__global__ __launch_bounds__(256) void softmax_kernel() {
    __shared__ float scs[En];
    const int warp = threadIdx.x >> 5;
    const int lane = threadIdx.x & 31;
    const int s = blockIdx.x * 8 + warp;

    if (threadIdx.x < En) scs[threadIdx.x] = 0.f;
    __syncthreads();

    const float* p0 = g_part + (size_t)s * En;
    const float* p1 = g_part + (size_t)(Sn * En) + (size_t)s * En;
    float v0 = p0[lane] + p1[lane];
    float v1 = p0[lane + 32] + p1[lane + 32];

    // row max
    float m = fmaxf(v0, v1);
#pragma unroll
    for (int o = 16; o; o >>= 1) m = fmaxf(m, __shfl_xor_sync(0xffffffffu, m, o));

    float e0 = expf(v0 - m), e1 = expf(v1 - m);
    float ss = e0 + e1;
#pragma unroll
    for (int o = 16; o; o >>= 1) ss += __shfl_xor_sync(0xffffffffu, ss, o);
    float inv = 1.0f / ss;
    float gg0 = e0 * inv, gg1 = e1 * inv;

    // argmax with tie-break: smallest index (matches jnp.argmax)
    float bv; int bi;
    if (v0 >= v1) { bv = v0; bi = lane; } else { bv = v1; bi = lane + 32; }
#pragma unroll
    for (int o = 16; o; o >>= 1) {
        float ov = __shfl_xor_sync(0xffffffffu, bv, o);
        int oi = __shfl_xor_sync(0xffffffffu, bi, o);
        if (ov > bv || (ov == bv && oi < bi)) { bv = ov; bi = oi; }
    }
    // gate value at argmax (bi is warp-uniform now)
    float gsel = __shfl_sync(0xffffffffu, (bi < 32) ? gg0 : gg1, bi & 31);

    // block-level column sums, then one global atomic per expert per block
    atomicAdd(&scs[lane], gg0);
    atomicAdd(&scs[lane + 32], gg1);

    if (lane == 0) {
        g_gate[s] = gsel;
        int p = atomicAdd(&g_cnt[bi], 1);
        if (p < MAXN) g_list[bi * MAXN + p] = s;
    }
    __syncthreads();
    if (threadIdx.x < En) atomicAdd(&g_colsum[threadIdx.x], scs[threadIdx.x]);
}

// ---------------- exact JAX threefry2x32 noise (partitionable path) ----------------
__device__ __forceinline__ unsigned rotl32(unsigned v, int d) {
    return (v << d) | (v >> (32 - d));
}
__device__ __forceinline__ float jax_noise(int s, int e) {
    unsigned x0 = 0u;
    unsigned x1 = (unsigned)(s * En + e);

    const unsigned ks0 = 0u;
    const unsigned ks1 = 42u;
    const unsigned ks2 = 0u ^ 42u ^ 0x1BD11BDAu;

    x0 += ks0; x1 += ks1;
#define TF_ROUND(R) { x0 += x1; x1 = rotl32(x1, R); x1 ^= x0; }
    TF_ROUND(13) TF_ROUND(15) TF_ROUND(26) TF_ROUND(6)
    x0 += ks1; x1 += ks2 + 1u;
    TF_ROUND(17) TF_ROUND(29) TF_ROUND(16) TF_ROUND(24)
    x0 += ks2; x1 += ks0 + 2u;
    TF_ROUND(13) TF_ROUND(15) TF_ROUND(26) TF_ROUND(6)
    x0 += ks0; x1 += ks1 + 3u;
    TF_ROUND(17) TF_ROUND(29) TF_ROUND(16) TF_ROUND(24)
    x0 += ks1; x1 += ks2 + 4u;
    TF_ROUND(13) TF_ROUND(15) TF_ROUND(26) TF_ROUND(6)
    x0 += ks2; x1 += ks0 + 5u;
#undef TF_ROUND
    unsigned bits = x0 ^ x1;
    return __uint_as_float((bits >> 9) | 0x3F800000u) - 1.0f;
}

// ---------------- per-expert capacity selection + direct scatter + finalize ----------------
// one block per expert; runs after the fill, so every write lands on zeros.
__global__ __launch_bounds__(256) void capacity_kernel(float* __restrict__ out,
                                                       long long out_size) {
    const int e = blockIdx.x;
    __shared__ int   sidx[MAXN];
    __shared__ float snoi[MAXN];
    __shared__ char  skeep[MAXN];
    __shared__ float sv[En];

    int n = g_cnt[e];
    if (n > MAXN) n = MAXN;

    for (int i = threadIdx.x; i < n; i += blockDim.x) {
        int s = g_list[e * MAXN + i];
        sidx[i] = s;
        snoi[i] = jax_noise(s, e);
    }
    __syncthreads();

    // keep = rank < capacity by (noise desc, index asc); lax.top_k is index-stable
    for (int i = threadIdx.x; i < n; i += blockDim.x) {
        char k = 1;
        if (n > Cn) {
            int r = 0;
            float ni = snoi[i];
            int ii = sidx[i];
            for (int jj = 0; jj < n; jj++) {
                float nj = snoi[jj];
                r += (nj > ni) || (nj == ni && sidx[jj] < ii);
            }
            k = (r < Cn) ? 1 : 0;
        }
        skeep[i] = k;
    }
    __syncthreads();

    // slot = rank by token index among kept (cumsum semantics); scatter outputs
    for (int i = threadIdx.x; i < n; i += blockDim.x) {
        if (!skeep[i]) continue;
        int ii = sidx[i];
        int slot = 0;
        for (int jj = 0; jj < n; jj++) slot += (skeep[jj] && sidx[jj] < ii);
        long long r = (long long)ii * En + e;
        long long p = 1 + r * (long long)Cn + slot;
        if (p < out_size) out[p] = g_gate[ii];
        if (p + SECn < out_size) out[p + SECn] = 1.0f;
    }

    // finalize fold-in: l_aux + exp_counts (block 0 only)
    if (e == 0) {
        int t = threadIdx.x;
        if (t < En) sv[t] = g_colsum[t] * (float)g_cnt[t];
        __syncthreads();
        if (t == 0) {
            float sum = 0.f;
            for (int i = 0; i < En; i++) sum += sv[i];
            float laux = sum * ((float)En / ((float)Sn * (float)Sn));
            if (out_size > 0) out[0] = laux;
        }
        long long idx = 1 + 2 * SECn + t;
        if (t < En && idx < out_size) out[idx] = (float)g_cnt[t];
    }
}

// ---------------- launch ----------------
extern "C" void kernel_launch(void* const* d_in, const int* in_sizes, int n_in,
                              void* d_out, int out_size) {
    const float* x  = (const float*)d_in[0];   // [S, D] f32
    const float* wg = (const float*)d_in[1];   // [E, D] f32
    float* out = (float*)d_out;
    long long osz = (long long)out_size;

    gemm_fill_kernel<<<TOTAL_BLOCKS, 256>>>(x, wg, out, osz);
    softmax_kernel<<<1024, 256>>>();
    capacity_kernel<<<En, 256>>>(out, osz);
}

// round 6
// speedup vs baseline: 1.2087x; 1.1370x over previous
#include <cuda_runtime.h>
#include <math.h>

// Problem constants
#define Sn 8192
#define Dn 2048
#define En 64
#define Cn 128
#define MAXN 1024   // max tokens gathered per expert (mean 128, sigma ~11)

#define GEMM_BLOCKS 128          // 64 M-tiles (128 tokens) x splitK 2
#define FILL_BLOCKS 896
#define TOTAL_BLOCKS (GEMM_BLOCKS + FILL_BLOCKS)

static const long long SECn = (long long)Sn * En * Cn;  // 67,108,864

// ---------------- device scratch (no allocations allowed) ----------------
__device__ float g_part[2 * Sn * En];   // split-K partial logits, 4MB
__device__ float g_gate[Sn];            // gate value at argmax expert
__device__ int   g_list[En * MAXN];     // per-expert gathered token indices
__device__ float g_colsum[En];          // column sums of gates (for me)
__device__ int   g_cnt[En];             // raw expert counts (mask1 sums)

// ---------------- fused GEMM + zero-fill (block specialization, wave-safe) ----------------
// Blocks 0..127: GEMM, tile 128 tokens x 64 experts, splitK=2, 8x4 register
// blocking (1.5 B/FMA from smem -> not crossbar-bound). Scheduled first ->
// all GEMM blocks land in wave 1, one per SM.
// Blocks 128..1023: contiguous-slice zero fill with streaming stores.
// Per-element K accumulation order identical to all passing rounds
// (ascending k within each half; halves summed p0+p1 in softmax).
__global__ __launch_bounds__(256) void gemm_fill_kernel(const float* __restrict__ x,
                                                        const float* __restrict__ wg,
                                                        float* __restrict__ out,
                                                        long long out_size) {
    const int bid = blockIdx.x;
    const int tid = threadIdx.x;

    if (bid >= GEMM_BLOCKS) {
        // ---- fill block: contiguous slice of the output ----
        const long long n4 = out_size >> 2;                       // float4 count
        const long long slice = (n4 + FILL_BLOCKS - 1) / FILL_BLOCKS;
        const long long fid = bid - GEMM_BLOCKS;                  // 0..895
        long long i = fid * slice + tid;
        long long end = fid * slice + slice;
        if (end > n4) end = n4;
        const float4 z4 = make_float4(0.f, 0.f, 0.f, 0.f);
#pragma unroll 4
        for (; i < end; i += 256)
            __stcs((float4*)(out + (i << 2)), z4);
        if (fid == 0 && tid == 0) {
            long long p = n4 << 2;                                // scalar tail
            if (p < out_size) out[p] = 0.f;
        }
        return;
    }

    // ---- GEMM block ----
    __shared__ float xsT[32][132];
    __shared__ float wsT[32][68];

    const int gid = bid;                     // 0..127
    const int m0 = (gid & 63) * 128;         // token tile base
    const int k0 = (gid >> 6) * 1024;        // split-K half

    if (gid == 0 && tid < En) {              // init fold-in
        g_colsum[tid] = 0.f;
        g_cnt[tid] = 0;
    }

    const int tx = tid & 15;   // expert group (4 experts)
    const int ty = tid >> 4;   // token group (8 tokens)

    float acc[8][4];
#pragma unroll
    for (int i = 0; i < 8; i++)
#pragma unroll
        for (int j = 0; j < 4; j++) acc[i][j] = 0.f;

    for (int kb = 0; kb < 1024; kb += 32) {
        // load x tile: 128 rows x 32 K = 1024 float4, 4 per thread
#pragma unroll
        for (int i = 0; i < 4; i++) {
            int v = tid + i * 256;       // 0..1023
            int row = v >> 3;            // 0..127
            int kq = v & 7;              // float4 along K
            const float4 xv = *(const float4*)(x + (size_t)(m0 + row) * Dn + (k0 + kb + (kq << 2)));
            xsT[(kq << 2) + 0][row] = xv.x;
            xsT[(kq << 2) + 1][row] = xv.y;
            xsT[(kq << 2) + 2][row] = xv.z;
            xsT[(kq << 2) + 3][row] = xv.w;
        }
        // load w tile: 64 rows x 32 K = 512 float4, 2 per thread
#pragma unroll
        for (int i = 0; i < 2; i++) {
            int v = tid + i * 256;       // 0..511
            int row = v >> 3;            // 0..63
            int kq = v & 7;
            const float4 wv = *(const float4*)(wg + (size_t)row * Dn + (k0 + kb + (kq << 2)));
            wsT[(kq << 2) + 0][row] = wv.x;
            wsT[(kq << 2) + 1][row] = wv.y;
            wsT[(kq << 2) + 2][row] = wv.z;
            wsT[(kq << 2) + 3][row] = wv.w;
        }
        __syncthreads();
#pragma unroll
        for (int kk = 0; kk < 32; kk++) {
            float4 a0 = *(const float4*)&xsT[kk][ty << 3];
            float4 a1 = *(const float4*)&xsT[kk][(ty << 3) + 4];
            float4 b  = *(const float4*)&wsT[kk][tx << 2];
            float av[8] = {a0.x, a0.y, a0.z, a0.w, a1.x, a1.y, a1.z, a1.w};
            float bv[4] = {b.x, b.y, b.z, b.w};
#pragma unroll
            for (int i = 0; i < 8; i++)
#pragma unroll
                for (int j = 0; j < 4; j++)
                    acc[i][j] = fmaf(av[i], bv[j], acc[i][j]);
        }
        __syncthreads();
    }

    float* op = g_part + (size_t)(gid >> 6) * (Sn * En);
#pragma unroll
    for (int i = 0; i < 8; i++) {
        float4 vv = make_float4(acc[i][0], acc[i][1], acc[i][2], acc[i][3]);
        *(float4*)(op + (size_t)(m0 + (ty << 3) + i) * En + (tx << 2)) = vv;
    }
}

// ---------------- softmax + argmax + column sums + counts + expert lists ----------------
// one warp per token, 8 tokens per block, 1024 blocks
__global__ __launch_bounds__(256) void softmax_kernel() {
    __shared__ float scs[En];
    const int warp = threadIdx.x >> 5;
    const int lane = threadIdx.x & 31;
    const int s = blockIdx.x * 8 + warp;

    if (threadIdx.x < En) scs[threadIdx.x] = 0.f;
    __syncthreads();

    const float* p0 = g_part + (size_t)s * En;
    const float* p1 = g_part + (size_t)(Sn * En) + (size_t)s * En;
    float v0 = p0[lane] + p1[lane];
    float v1 = p0[lane + 32] + p1[lane + 32];

    // row max
    float m = fmaxf(v0, v1);
#pragma unroll
    for (int o = 16; o; o >>= 1) m = fmaxf(m, __shfl_xor_sync(0xffffffffu, m, o));

    float e0 = expf(v0 - m), e1 = expf(v1 - m);
    float ss = e0 + e1;
#pragma unroll
    for (int o = 16; o; o >>= 1) ss += __shfl_xor_sync(0xffffffffu, ss, o);
    float inv = 1.0f / ss;
    float gg0 = e0 * inv, gg1 = e1 * inv;

    // argmax with tie-break: smallest index (matches jnp.argmax)
    float bv; int bi;
    if (v0 >= v1) { bv = v0; bi = lane; } else { bv = v1; bi = lane + 32; }
#pragma unroll
    for (int o = 16; o; o >>= 1) {
        float ov = __shfl_xor_sync(0xffffffffu, bv, o);
        int oi = __shfl_xor_sync(0xffffffffu, bi, o);
        if (ov > bv || (ov == bv && oi < bi)) { bv = ov; bi = oi; }
    }
    // gate value at argmax (bi is warp-uniform now)
    float gsel = __shfl_sync(0xffffffffu, (bi < 32) ? gg0 : gg1, bi & 31);

    // block-level column sums, then one global atomic per expert per block
    atomicAdd(&scs[lane], gg0);
    atomicAdd(&scs[lane + 32], gg1);

    if (lane == 0) {
        g_gate[s] = gsel;
        int p = atomicAdd(&g_cnt[bi], 1);
        if (p < MAXN) g_list[bi * MAXN + p] = s;
    }
    __syncthreads();
    if (threadIdx.x < En) atomicAdd(&g_colsum[threadIdx.x], scs[threadIdx.x]);
}

// ---------------- exact JAX threefry2x32 noise (partitionable path) ----------------
__device__ __forceinline__ unsigned rotl32(unsigned v, int d) {
    return (v << d) | (v >> (32 - d));
}
__device__ __forceinline__ float jax_noise(int s, int e) {
    unsigned x0 = 0u;
    unsigned x1 = (unsigned)(s * En + e);

    const unsigned ks0 = 0u;
    const unsigned ks1 = 42u;
    const unsigned ks2 = 0u ^ 42u ^ 0x1BD11BDAu;

    x0 += ks0; x1 += ks1;
#define TF_ROUND(R) { x0 += x1; x1 = rotl32(x1, R); x1 ^= x0; }
    TF_ROUND(13) TF_ROUND(15) TF_ROUND(26) TF_ROUND(6)
    x0 += ks1; x1 += ks2 + 1u;
    TF_ROUND(17) TF_ROUND(29) TF_ROUND(16) TF_ROUND(24)
    x0 += ks2; x1 += ks0 + 2u;
    TF_ROUND(13) TF_ROUND(15) TF_ROUND(26) TF_ROUND(6)
    x0 += ks0; x1 += ks1 + 3u;
    TF_ROUND(17) TF_ROUND(29) TF_ROUND(16) TF_ROUND(24)
    x0 += ks1; x1 += ks2 + 4u;
    TF_ROUND(13) TF_ROUND(15) TF_ROUND(26) TF_ROUND(6)
    x0 += ks2; x1 += ks0 + 5u;
#undef TF_ROUND
    unsigned bits = x0 ^ x1;
    return __uint_as_float((bits >> 9) | 0x3F800000u) - 1.0f;
}

// ---------------- per-expert capacity selection + direct scatter + finalize ----------------
// one block per expert; runs after the fill, so every write lands on zeros.
__global__ __launch_bounds__(256) void capacity_kernel(float* __restrict__ out,
                                                       long long out_size) {
    const int e = blockIdx.x;
    __shared__ int   sidx[MAXN];
    __shared__ float snoi[MAXN];
    __shared__ char  skeep[MAXN];
    __shared__ float sv[En];

    int n = g_cnt[e];
    if (n > MAXN) n = MAXN;

    for (int i = threadIdx.x; i < n; i += blockDim.x) {
        int s = g_list[e * MAXN + i];
        sidx[i] = s;
        snoi[i] = jax_noise(s, e);
    }
    __syncthreads();

    // keep = rank < capacity by (noise desc, index asc); lax.top_k is index-stable
    for (int i = threadIdx.x; i < n; i += blockDim.x) {
        char k = 1;
        if (n > Cn) {
            int r = 0;
            float ni = snoi[i];
            int ii = sidx[i];
            for (int jj = 0; jj < n; jj++) {
                float nj = snoi[jj];
                r += (nj > ni) || (nj == ni && sidx[jj] < ii);
            }
            k = (r < Cn) ? 1 : 0;
        }
        skeep[i] = k;
    }
    __syncthreads();

    // slot = rank by token index among kept (cumsum semantics); scatter outputs
    for (int i = threadIdx.x; i < n; i += blockDim.x) {
        if (!skeep[i]) continue;
        int ii = sidx[i];
        int slot = 0;
        for (int jj = 0; jj < n; jj++) slot += (skeep[jj] && sidx[jj] < ii);
        long long r = (long long)ii * En + e;
        long long p = 1 + r * (long long)Cn + slot;
        if (p < out_size) out[p] = g_gate[ii];
        if (p + SECn < out_size) out[p + SECn] = 1.0f;
    }

    // finalize fold-in: l_aux + exp_counts (block 0 only)
    if (e == 0) {
        int t = threadIdx.x;
        if (t < En) sv[t] = g_colsum[t] * (float)g_cnt[t];
        __syncthreads();
        if (t == 0) {
            float sum = 0.f;
            for (int i = 0; i < En; i++) sum += sv[i];
            float laux = sum * ((float)En / ((float)Sn * (float)Sn));
            if (out_size > 0) out[0] = laux;
        }
        long long idx = 1 + 2 * SECn + t;
        if (t < En && idx < out_size) out[idx] = (float)g_cnt[t];
    }
}

// ---------------- launch ----------------
extern "C" void kernel_launch(void* const* d_in, const int* in_sizes, int n_in,
                              void* d_out, int out_size) {
    const float* x  = (const float*)d_in[0];   // [S, D] f32
    const float* wg = (const float*)d_in[1];   // [E, D] f32
    float* out = (float*)d_out;
    long long osz = (long long)out_size;

    gemm_fill_kernel<<<TOTAL_BLOCKS, 256>>>(x, wg, out, osz);
    softmax_kernel<<<1024, 256>>>();
    capacity_kernel<<<En, 256>>>(out, osz);
}

// round 7
// speedup vs baseline: 1.3099x; 1.0837x over previous
#include <cuda_runtime.h>
#include <math.h>

// Problem constants
#define Sn 8192
#define Dn 2048
#define En 64
#define Cn 128
#define MAXN 1024   // max tokens gathered per expert (mean 128, sigma ~11)

#define GEMM_BLOCKS 128          // 64 M-tiles (128 tokens) x splitK 2
#define TOTAL_BLOCKS 296         // exactly 2 blocks per SM (148 SMs)

static const long long SECn = (long long)Sn * En * Cn;  // 67,108,864

// ---------------- device scratch (no allocations allowed) ----------------
__device__ float g_part[2 * Sn * En];   // split-K partial logits, 4MB
__device__ float g_gate[Sn];            // gate value at argmax expert
__device__ int   g_list[En * MAXN];     // per-expert gathered token indices
__device__ float g_colsum[En];          // column sums of gates (for me)
__device__ int   g_cnt[En];             // raw expert counts (mask1 sums)

// packed f32x2 helpers (per-lane identical to fmaf -> bit-faithful logits)
__device__ __forceinline__ unsigned long long pk2(float lo, float hi) {
    unsigned long long r;
    asm("mov.b64 %0, {%1, %2};" : "=l"(r) : "f"(lo), "f"(hi));
    return r;
}
__device__ __forceinline__ void fma2(unsigned long long& d, unsigned long long a,
                                     unsigned long long b) {
    asm("fma.rn.f32x2 %0, %1, %2, %0;" : "+l"(d) : "l"(a), "l"(b));
}
__device__ __forceinline__ void upk2(float& lo, float& hi, unsigned long long v) {
    asm("mov.b64 {%0, %1}, %2;" : "=f"(lo), "=f"(hi) : "l"(v));
}

// ---------------- fused GEMM + zero-fill ----------------
// 296 blocks x 256 threads, 2 blocks/SM guaranteed -> single wave.
// Blocks 0..127: GEMM 128tok x 64exp, splitK=2, f32x2 8x4 per-thread tile,
//   with its fill slice interleaved per k-chunk (R3-proven overlap pattern).
// Blocks 128..295: pure streaming zero-fill of their slice.
// Every block fills a contiguous 1/296 slice of the output.
__global__ __launch_bounds__(256, 2) void gemm_fill_kernel(const float* __restrict__ x,
                                                           const float* __restrict__ wg,
                                                           float* __restrict__ out,
                                                           long long out_size) {
    const int bid = blockIdx.x;
    const int tid = threadIdx.x;

    const long long n4 = out_size >> 2;                        // float4 count
    const long long slice = (n4 + TOTAL_BLOCKS - 1) / TOTAL_BLOCKS;
    long long lo = (long long)bid * slice;
    long long hi = lo + slice;
    if (hi > n4) hi = n4;
    const float4 z4 = make_float4(0.f, 0.f, 0.f, 0.f);

    if (bid >= GEMM_BLOCKS) {
        // ---- pure fill block ----
#pragma unroll 4
        for (long long i = lo + tid; i < hi; i += 256)
            __stcs((float4*)(out + (i << 2)), z4);
        if (bid == TOTAL_BLOCKS - 1 && tid == 0) {
            long long p = n4 << 2;                             // scalar tail
            if (p < out_size) out[p] = 0.f;
        }
        return;
    }

    // ---- GEMM block (+ interleaved fill) ----
    __shared__ float xsT[32][132];
    __shared__ float wsT[32][68];

    const int gid = bid;                     // 0..127
    const int m0 = (gid & 63) * 128;         // token tile base
    const int k0 = (gid >> 6) * 1024;        // split-K half

    if (gid == 0 && tid < En) {              // init fold-in
        g_colsum[tid] = 0.f;
        g_cnt[tid] = 0;
    }

    const int tx = tid & 15;   // expert group (4 experts)
    const int ty = tid >> 4;   // token group (8 tokens)
    const long long per_chunk = (slice + 31) / 32;

    unsigned long long acc2[4][4];           // [token-pair][expert], f32x2
#pragma unroll
    for (int i = 0; i < 4; i++)
#pragma unroll
        for (int j = 0; j < 4; j++) acc2[i][j] = 0ull;

    for (int kb = 0; kb < 1024; kb += 32) {
        // load x tile: 128 rows x 32 K = 1024 float4, 4 per thread (transposed)
#pragma unroll
        for (int i = 0; i < 4; i++) {
            int v = tid + i * 256;       // 0..1023
            int row = v >> 3;            // 0..127
            int kq = v & 7;              // float4 along K
            const float4 xv = *(const float4*)(x + (size_t)(m0 + row) * Dn + (k0 + kb + (kq << 2)));
            xsT[(kq << 2) + 0][row] = xv.x;
            xsT[(kq << 2) + 1][row] = xv.y;
            xsT[(kq << 2) + 2][row] = xv.z;
            xsT[(kq << 2) + 3][row] = xv.w;
        }
        // load w tile: 64 rows x 32 K = 512 float4, 2 per thread (transposed)
#pragma unroll
        for (int i = 0; i < 2; i++) {
            int v = tid + i * 256;       // 0..511
            int row = v >> 3;            // 0..63
            int kq = v & 7;
            const float4 wv = *(const float4*)(wg + (size_t)row * Dn + (k0 + kb + (kq << 2)));
            wsT[(kq << 2) + 0][row] = wv.x;
            wsT[(kq << 2) + 1][row] = wv.y;
            wsT[(kq << 2) + 2][row] = wv.z;
            wsT[(kq << 2) + 3][row] = wv.w;
        }
        __syncthreads();

        // interleaved fill: this chunk's sub-range of the block's slice
        {
            int c = kb >> 5;                               // 0..31
            long long s0 = lo + (long long)c * per_chunk;
            long long s1 = s0 + per_chunk;
            if (s1 > hi) s1 = hi;
            for (long long i = s0 + tid; i < s1; i += 256)
                __stcs((float4*)(out + (i << 2)), z4);
        }

#pragma unroll
        for (int kk = 0; kk < 32; kk++) {
            float4 a0 = *(const float4*)&xsT[kk][ty << 3];
            float4 a1 = *(const float4*)&xsT[kk][(ty << 3) + 4];
            float4 b  = *(const float4*)&wsT[kk][tx << 2];
            unsigned long long av2[4] = {pk2(a0.x, a0.y), pk2(a0.z, a0.w),
                                         pk2(a1.x, a1.y), pk2(a1.z, a1.w)};
            unsigned long long bv2[4] = {pk2(b.x, b.x), pk2(b.y, b.y),
                                         pk2(b.z, b.z), pk2(b.w, b.w)};
#pragma unroll
            for (int i = 0; i < 4; i++)
#pragma unroll
                for (int j = 0; j < 4; j++)
                    fma2(acc2[i][j], av2[i], bv2[j]);
        }
        __syncthreads();
    }

    // unpack and store partial logits
    float* op = g_part + (size_t)(gid >> 6) * (Sn * En);
#pragma unroll
    for (int i = 0; i < 4; i++) {
        float l0, h0, l1, h1, l2, h2, l3, h3;
        upk2(l0, h0, acc2[i][0]);
        upk2(l1, h1, acc2[i][1]);
        upk2(l2, h2, acc2[i][2]);
        upk2(l3, h3, acc2[i][3]);
        float4 vlo = make_float4(l0, l1, l2, l3);   // token 2i
        float4 vhi = make_float4(h0, h1, h2, h3);   // token 2i+1
        *(float4*)(op + (size_t)(m0 + (ty << 3) + 2 * i) * En + (tx << 2)) = vlo;
        *(float4*)(op + (size_t)(m0 + (ty << 3) + 2 * i + 1) * En + (tx << 2)) = vhi;
    }
}

// ---------------- softmax + argmax + column sums + counts + expert lists ----------------
// one warp per token, 8 tokens per block, 1024 blocks
__global__ __launch_bounds__(256) void softmax_kernel() {
    __shared__ float scs[En];
    const int warp = threadIdx.x >> 5;
    const int lane = threadIdx.x & 31;
    const int s = blockIdx.x * 8 + warp;

    if (threadIdx.x < En) scs[threadIdx.x] = 0.f;
    __syncthreads();

    const float* p0 = g_part + (size_t)s * En;
    const float* p1 = g_part + (size_t)(Sn * En) + (size_t)s * En;
    float v0 = p0[lane] + p1[lane];
    float v1 = p0[lane + 32] + p1[lane + 32];

    // row max
    float m = fmaxf(v0, v1);
#pragma unroll
    for (int o = 16; o; o >>= 1) m = fmaxf(m, __shfl_xor_sync(0xffffffffu, m, o));

    float e0 = expf(v0 - m), e1 = expf(v1 - m);
    float ss = e0 + e1;
#pragma unroll
    for (int o = 16; o; o >>= 1) ss += __shfl_xor_sync(0xffffffffu, ss, o);
    float inv = 1.0f / ss;
    float gg0 = e0 * inv, gg1 = e1 * inv;

    // argmax with tie-break: smallest index (matches jnp.argmax)
    float bv; int bi;
    if (v0 >= v1) { bv = v0; bi = lane; } else { bv = v1; bi = lane + 32; }
#pragma unroll
    for (int o = 16; o; o >>= 1) {
        float ov = __shfl_xor_sync(0xffffffffu, bv, o);
        int oi = __shfl_xor_sync(0xffffffffu, bi, o);
        if (ov > bv || (ov == bv && oi < bi)) { bv = ov; bi = oi; }
    }
    // gate value at argmax (bi is warp-uniform now)
    float gsel = __shfl_sync(0xffffffffu, (bi < 32) ? gg0 : gg1, bi & 31);

    // block-level column sums, then one global atomic per expert per block
    atomicAdd(&scs[lane], gg0);
    atomicAdd(&scs[lane + 32], gg1);

    if (lane == 0) {
        g_gate[s] = gsel;
        int p = atomicAdd(&g_cnt[bi], 1);
        if (p < MAXN) g_list[bi * MAXN + p] = s;
    }
    __syncthreads();
    if (threadIdx.x < En) atomicAdd(&g_colsum[threadIdx.x], scs[threadIdx.x]);
}

// ---------------- exact JAX threefry2x32 noise (partitionable path) ----------------
__device__ __forceinline__ unsigned rotl32(unsigned v, int d) {
    return (v << d) | (v >> (32 - d));
}
__device__ __forceinline__ float jax_noise(int s, int e) {
    unsigned x0 = 0u;
    unsigned x1 = (unsigned)(s * En + e);

    const unsigned ks0 = 0u;
    const unsigned ks1 = 42u;
    const unsigned ks2 = 0u ^ 42u ^ 0x1BD11BDAu;

    x0 += ks0; x1 += ks1;
#define TF_ROUND(R) { x0 += x1; x1 = rotl32(x1, R); x1 ^= x0; }
    TF_ROUND(13) TF_ROUND(15) TF_ROUND(26) TF_ROUND(6)
    x0 += ks1; x1 += ks2 + 1u;
    TF_ROUND(17) TF_ROUND(29) TF_ROUND(16) TF_ROUND(24)
    x0 += ks2; x1 += ks0 + 2u;
    TF_ROUND(13) TF_ROUND(15) TF_ROUND(26) TF_ROUND(6)
    x0 += ks0; x1 += ks1 + 3u;
    TF_ROUND(17) TF_ROUND(29) TF_ROUND(16) TF_ROUND(24)
    x0 += ks1; x1 += ks2 + 4u;
    TF_ROUND(13) TF_ROUND(15) TF_ROUND(26) TF_ROUND(6)
    x0 += ks2; x1 += ks0 + 5u;
#undef TF_ROUND
    unsigned bits = x0 ^ x1;
    return __uint_as_float((bits >> 9) | 0x3F800000u) - 1.0f;
}

// ---------------- per-expert capacity selection + direct scatter + finalize ----------------
// one block per expert; runs after the fill, so every write lands on zeros.
__global__ __launch_bounds__(256) void capacity_kernel(float* __restrict__ out,
                                                       long long out_size) {
    const int e = blockIdx.x;
    __shared__ int   sidx[MAXN];
    __shared__ float snoi[MAXN];
    __shared__ char  skeep[MAXN];
    __shared__ float sv[En];

    int n = g_cnt[e];
    if (n > MAXN) n = MAXN;

    for (int i = threadIdx.x; i < n; i += blockDim.x) {
        int s = g_list[e * MAXN + i];
        sidx[i] = s;
        snoi[i] = jax_noise(s, e);
    }
    __syncthreads();

    // keep = rank < capacity by (noise desc, index asc); lax.top_k is index-stable
    for (int i = threadIdx.x; i < n; i += blockDim.x) {
        char k = 1;
        if (n > Cn) {
            int r = 0;
            float ni = snoi[i];
            int ii = sidx[i];
            for (int jj = 0; jj < n; jj++) {
                float nj = snoi[jj];
                r += (nj > ni) || (nj == ni && sidx[jj] < ii);
            }
            k = (r < Cn) ? 1 : 0;
        }
        skeep[i] = k;
    }
    __syncthreads();

    // slot = rank by token index among kept (cumsum semantics); scatter outputs
    for (int i = threadIdx.x; i < n; i += blockDim.x) {
        if (!skeep[i]) continue;
        int ii = sidx[i];
        int slot = 0;
        for (int jj = 0; jj < n; jj++) slot += (skeep[jj] && sidx[jj] < ii);
        long long r = (long long)ii * En + e;
        long long p = 1 + r * (long long)Cn + slot;
        if (p < out_size) out[p] = g_gate[ii];
        if (p + SECn < out_size) out[p + SECn] = 1.0f;
    }

    // finalize fold-in: l_aux + exp_counts (block 0 only)
    if (e == 0) {
        int t = threadIdx.x;
        if (t < En) sv[t] = g_colsum[t] * (float)g_cnt[t];
        __syncthreads();
        if (t == 0) {
            float sum = 0.f;
            for (int i = 0; i < En; i++) sum += sv[i];
            float laux = sum * ((float)En / ((float)Sn * (float)Sn));
            if (out_size > 0) out[0] = laux;
        }
        long long idx = 1 + 2 * SECn + t;
        if (t < En && idx < out_size) out[idx] = (float)g_cnt[t];
    }
}

// ---------------- launch ----------------
extern "C" void kernel_launch(void* const* d_in, const int* in_sizes, int n_in,
                              void* d_out, int out_size) {
    const float* x  = (const float*)d_in[0];   // [S, D] f32
    const float* wg = (const float*)d_in[1];   // [E, D] f32
    float* out = (float*)d_out;
    long long osz = (long long)out_size;

    gemm_fill_kernel<<<TOTAL_BLOCKS, 256>>>(x, wg, out, osz);
    softmax_kernel<<<1024, 256>>>();
    capacity_kernel<<<En, 256>>>(out, osz);
}